// round 2
// baseline (speedup 1.0000x reference)
#include <cuda_runtime.h>
#include <cuda_bf16.h>

// Shapes
#define TT 512
#define BB 16
#define DM 512
#define NH 8
#define HD 64
#define DFF 2048
#define NROW (TT*BB)          // 8192
#define EPS_BN 1.28402541668774148407f  // exp(0.25)

// ---------------- scratch (device globals; no allocation allowed) ----------------
__device__ float g_x[NROW*DM];
__device__ float g_hid[NROW*DFF];
__device__ float g_qkv[NROW*3*DM];
__device__ float g_pospad[1024*DM];
__device__ float g_p[1024*DM];
__device__ float g_scores[128*512*512];   // (B*H, T, T) fp32
__device__ float g_buf1[NROW*DM];
__device__ float g_buf2[NROW*DM];

// ---------------- SGEMM: C[N,M] = act(A[N,K] @ W[M,K]^T + bias) (+res) ----------------
// N, M multiples of 128; K multiple of 8.
__global__ __launch_bounds__(256) void sgemm_kernel(
    const float* __restrict__ A, const float* __restrict__ W,
    const float* __restrict__ bias, const float* __restrict__ res,
    float* __restrict__ C, int N, int K, int M, int act)
{
    __shared__ float As[8][128];
    __shared__ float Bs[8][128];
    int tid = threadIdx.x;
    int n0 = blockIdx.y * 128;
    int m0 = blockIdx.x * 128;
    int lrow = tid >> 1;
    int lcol = (tid & 1) << 2;
    const float* Aptr = A + (n0 + lrow) * K + lcol;
    const float* Wptr = W + (m0 + lrow) * K + lcol;
    int tx = tid & 15, ty = tid >> 4;
    float acc[8][8];
#pragma unroll
    for (int i = 0; i < 8; i++)
#pragma unroll
        for (int j = 0; j < 8; j++) acc[i][j] = 0.f;

    for (int k0 = 0; k0 < K; k0 += 8) {
        float4 av = *(const float4*)(Aptr + k0);
        float4 wv = *(const float4*)(Wptr + k0);
        As[lcol + 0][lrow] = av.x; As[lcol + 1][lrow] = av.y;
        As[lcol + 2][lrow] = av.z; As[lcol + 3][lrow] = av.w;
        Bs[lcol + 0][lrow] = wv.x; Bs[lcol + 1][lrow] = wv.y;
        Bs[lcol + 2][lrow] = wv.z; Bs[lcol + 3][lrow] = wv.w;
        __syncthreads();
#pragma unroll
        for (int kk = 0; kk < 8; kk++) {
            float4 a0 = *(const float4*)&As[kk][ty * 4];
            float4 a1 = *(const float4*)&As[kk][ty * 4 + 64];
            float4 b0 = *(const float4*)&Bs[kk][tx * 4];
            float4 b1 = *(const float4*)&Bs[kk][tx * 4 + 64];
            float ar[8] = {a0.x, a0.y, a0.z, a0.w, a1.x, a1.y, a1.z, a1.w};
            float br[8] = {b0.x, b0.y, b0.z, b0.w, b1.x, b1.y, b1.z, b1.w};
#pragma unroll
            for (int i = 0; i < 8; i++)
#pragma unroll
                for (int j = 0; j < 8; j++) acc[i][j] += ar[i] * br[j];
        }
        __syncthreads();
    }
#pragma unroll
    for (int i = 0; i < 8; i++) {
        int row = n0 + ty * 4 + (i < 4 ? i : 60 + i);
#pragma unroll
        for (int j = 0; j < 8; j++) {
            int col = m0 + tx * 4 + (j < 4 ? j : 60 + j);
            float v = acc[i][j] + (bias ? bias[col] : 0.f);
            if (act) v = v / (1.f + __expf(1.f - v));   // double_swish: x*sigmoid(x-1)
            if (res) v += res[row * M + col];
            C[row * M + col] = v;
        }
    }
}

// ---------------- pos_emb pad to 1024 rows ----------------
__global__ void pospad_kernel(const float* __restrict__ pe, float* __restrict__ out) {
    int idx = blockIdx.x * 256 + threadIdx.x;   // 1024*512
    out[idx] = (idx < 1023 * DM) ? pe[idx] : 0.f;
}

// ---------------- fused rel-pos attention scores: ac + rel_shift(bd) ----------------
// scores[bh, t, s] = dot(q*0.125 + u, k[s]) + dot(q*0.125 + v, p[h, T-1-t+s])
__global__ __launch_bounds__(256) void scores_kernel(
    const float* __restrict__ qkv, const float* __restrict__ p,
    const float* __restrict__ ub, const float* __restrict__ vb,
    float* __restrict__ scores)
{
    __shared__ float squ[32][65], sqv[32][65], sk[32][65], sp[63][65];
    int bh = blockIdx.z; int b = bh >> 3; int h = bh & 7;
    int t0 = blockIdx.y * 32, s0 = blockIdx.x * 32;
    int tid = threadIdx.x;
#pragma unroll
    for (int i = 0; i < 8; i++) {
        int idx = tid + i * 256; int tl = idx >> 6; int d = idx & 63;
        float q = qkv[((t0 + tl) * BB + b) * (3 * DM) + h * HD + d] * 0.125f;
        squ[tl][d] = q + ub[h * HD + d];
        sqv[tl][d] = q + vb[h * HD + d];
        sk[tl][d]  = qkv[((s0 + tl) * BB + b) * (3 * DM) + DM + h * HD + d];
    }
    int base = (TT - 1) - (t0 + 31) + s0;   // 480 - t0 + s0, in [0, 960]
#pragma unroll
    for (int i = 0; i < 16; i++) {
        int idx = tid + i * 256;
        if (idx < 63 * 64) {
            int r = idx >> 6; int d = idx & 63;
            sp[r][d] = p[(base + r) * DM + h * HD + d];
        }
    }
    __syncthreads();
    int r = tid >> 4, c = tid & 15;
    float a00 = 0, a01 = 0, a10 = 0, a11 = 0;
#pragma unroll
    for (int d = 0; d < 64; d++) {
        float qu0 = squ[r][d],      qu1 = squ[r + 16][d];
        float qv0 = sqv[r][d],      qv1 = sqv[r + 16][d];
        float k0  = sk[c][d],       k1  = sk[c + 16][d];
        float p00 = sp[31 - r + c][d],      p01 = sp[31 - r + c + 16][d];
        float p10 = sp[15 - r + c][d],      p11 = sp[15 - r + c + 16][d];
        a00 += qu0 * k0 + qv0 * p00;
        a01 += qu0 * k1 + qv0 * p01;
        a10 += qu1 * k0 + qv1 * p10;
        a11 += qu1 * k1 + qv1 * p11;
    }
    float* out = scores + ((long)bh * TT) * TT;
    out[(t0 + r) * TT + s0 + c]            = a00;
    out[(t0 + r) * TT + s0 + c + 16]       = a01;
    out[(t0 + r + 16) * TT + s0 + c]       = a10;
    out[(t0 + r + 16) * TT + s0 + c + 16]  = a11;
}

// ---------------- softmax over last dim (512), in place ----------------
__global__ __launch_bounds__(128) void softmax_kernel(float* __restrict__ scores) {
    long row = blockIdx.x;
    float* x = scores + row * TT;
    int tid = threadIdx.x;
    __shared__ float red[128];
    float v[4];
    float m = -1e30f;
#pragma unroll
    for (int i = 0; i < 4; i++) { v[i] = x[tid + i * 128]; m = fmaxf(m, v[i]); }
    red[tid] = m; __syncthreads();
    for (int s = 64; s > 0; s >>= 1) { if (tid < s) red[tid] = fmaxf(red[tid], red[tid + s]); __syncthreads(); }
    m = red[0];
    float sum = 0.f;
#pragma unroll
    for (int i = 0; i < 4; i++) { v[i] = __expf(v[i] - m); sum += v[i]; }
    __syncthreads();
    red[tid] = sum; __syncthreads();
    for (int s = 64; s > 0; s >>= 1) { if (tid < s) red[tid] += red[tid + s]; __syncthreads(); }
    float inv = 1.f / red[0];
#pragma unroll
    for (int i = 0; i < 4; i++) x[tid + i * 128] = v[i] * inv;
}

// ---------------- attn @ V -> (T*B, DM) layout ----------------
__global__ __launch_bounds__(256) void attnv_kernel(
    const float* __restrict__ scores, const float* __restrict__ qkv, float* __restrict__ out)
{
    __shared__ float sa[64][33], sv[32][65];
    int bh = blockIdx.y; int b = bh >> 3, h = bh & 7;
    int t0 = blockIdx.x * 64;
    int tid = threadIdx.x;
    int tx = tid & 15, ty = tid >> 4;
    float acc[4][4];
#pragma unroll
    for (int i = 0; i < 4; i++)
#pragma unroll
        for (int j = 0; j < 4; j++) acc[i][j] = 0.f;
    const float* S = scores + ((long)bh * TT + t0) * TT;
    for (int sblk = 0; sblk < TT; sblk += 32) {
#pragma unroll
        for (int i = 0; i < 8; i++) {
            int idx = tid + i * 256; int rr = idx >> 5; int cc = idx & 31;
            sa[rr][cc] = S[rr * TT + sblk + cc];
        }
#pragma unroll
        for (int i = 0; i < 8; i++) {
            int idx = tid + i * 256; int rr = idx >> 6; int dd = idx & 63;
            sv[rr][dd] = qkv[((sblk + rr) * BB + b) * (3 * DM) + 2 * DM + h * HD + dd];
        }
        __syncthreads();
#pragma unroll
        for (int s = 0; s < 32; s++) {
            float a[4], vv[4];
#pragma unroll
            for (int i = 0; i < 4; i++) a[i] = sa[ty * 4 + i][s];
#pragma unroll
            for (int j = 0; j < 4; j++) vv[j] = sv[s][tx * 4 + j];
#pragma unroll
            for (int i = 0; i < 4; i++)
#pragma unroll
                for (int j = 0; j < 4; j++) acc[i][j] += a[i] * vv[j];
        }
        __syncthreads();
    }
#pragma unroll
    for (int i = 0; i < 4; i++) {
        int t = t0 + ty * 4 + i;
#pragma unroll
        for (int j = 0; j < 4; j++) {
            int d = tx * 4 + j;
            out[(t * BB + b) * DM + h * HD + d] = acc[i][j];
        }
    }
}

// ---------------- GLU over channel dim ----------------
__global__ void glu_kernel(const float* __restrict__ in, float* __restrict__ out) {
    int idx = blockIdx.x * 256 + threadIdx.x;      // NROW*512
    int row = idx >> 9, c = idx & 511;
    float a = in[row * 1024 + c], g = in[row * 1024 + 512 + c];
    out[idx] = a / (1.f + __expf(-g));
}

// ---------------- depthwise causal conv (K=31) + bias + double_swish ----------------
__global__ void dwconv_kernel(const float* __restrict__ x, const float* __restrict__ w,
                              const float* __restrict__ bias, float* __restrict__ out) {
    int idx = blockIdx.x * 256 + threadIdx.x;      // NROW*512
    int c = idx & 511;
    int tb = idx >> 9; int b = tb & 15; int t = tb >> 4;
    float acc = bias[c];
#pragma unroll
    for (int j = 0; j < 31; j++) {
        int tt = t - 30 + j;
        if (tt >= 0) acc += w[c * 31 + j] * x[(tt * BB + b) * DM + c];
    }
    out[idx] = acc / (1.f + __expf(1.f - acc));
}

// ---------------- BasicNorm ----------------
__global__ __launch_bounds__(128) void norm_kernel(const float* __restrict__ x, float* __restrict__ out) {
    int row = blockIdx.x; int tid = threadIdx.x;
    const float* xr = x + row * DM;
    __shared__ float red[128];
    float v[4]; float s = 0.f;
#pragma unroll
    for (int i = 0; i < 4; i++) { v[i] = xr[tid + i * 128]; s += v[i] * v[i]; }
    red[tid] = s; __syncthreads();
    for (int k = 64; k > 0; k >>= 1) { if (tid < k) red[tid] += red[tid + k]; __syncthreads(); }
    float scale = rsqrtf(red[0] * (1.f / DM) + EPS_BN);
#pragma unroll
    for (int i = 0; i < 4; i++) out[row * DM + tid + i * 128] = v[i] * scale;
}

// ---------------- launch ----------------
extern "C" void kernel_launch(void* const* d_in, const int* in_sizes, int n_in,
                              void* d_out, int out_size) {
    const float* src        = (const float*)d_in[0];
    const float* pos_emb    = (const float*)d_in[1];
    const float* ffm_w1     = (const float*)d_in[2];
    const float* ffm_b1     = (const float*)d_in[3];
    const float* ffm_w2     = (const float*)d_in[4];
    const float* ffm_b2     = (const float*)d_in[5];
    const float* ff_w1      = (const float*)d_in[6];
    const float* ff_b1      = (const float*)d_in[7];
    const float* ff_w2      = (const float*)d_in[8];
    const float* ff_b2      = (const float*)d_in[9];
    const float* in_proj_w  = (const float*)d_in[10];
    const float* in_proj_b  = (const float*)d_in[11];
    const float* out_proj_w = (const float*)d_in[12];
    const float* out_proj_b = (const float*)d_in[13];
    const float* linear_pos_w = (const float*)d_in[14];
    const float* pos_bias_u = (const float*)d_in[15];
    const float* pos_bias_v = (const float*)d_in[16];
    const float* conv_pw1_w = (const float*)d_in[17];
    const float* conv_pw1_b = (const float*)d_in[18];
    const float* conv_dw_w  = (const float*)d_in[19];
    const float* conv_dw_b  = (const float*)d_in[20];
    const float* conv_pw2_w = (const float*)d_in[21];
    const float* conv_pw2_b = (const float*)d_in[22];

    float *x, *hid, *qkv, *pospad, *p, *scores, *buf1, *buf2;
    cudaGetSymbolAddress((void**)&x, g_x);
    cudaGetSymbolAddress((void**)&hid, g_hid);
    cudaGetSymbolAddress((void**)&qkv, g_qkv);
    cudaGetSymbolAddress((void**)&pospad, g_pospad);
    cudaGetSymbolAddress((void**)&p, g_p);
    cudaGetSymbolAddress((void**)&scores, g_scores);
    cudaGetSymbolAddress((void**)&buf1, g_buf1);
    cudaGetSymbolAddress((void**)&buf2, g_buf2);

    // 1. macaron FFW
    sgemm_kernel<<<dim3(DFF / 128, NROW / 128), 256>>>(src, ffm_w1, ffm_b1, nullptr, hid, NROW, DM, DFF, 1);
    sgemm_kernel<<<dim3(DM / 128, NROW / 128), 256>>>(hid, ffm_w2, ffm_b2, src, x, NROW, DFF, DM, 0);

    // 2. attention projections
    sgemm_kernel<<<dim3(3 * DM / 128, NROW / 128), 256>>>(x, in_proj_w, in_proj_b, nullptr, qkv, NROW, DM, 3 * DM, 0);
    pospad_kernel<<<(1024 * DM) / 256, 256>>>(pos_emb, pospad);
    sgemm_kernel<<<dim3(DM / 128, 1024 / 128), 256>>>(pospad, linear_pos_w, nullptr, nullptr, p, 1024, DM, DM, 0);

    // 3. scores + softmax + attn@V
    scores_kernel<<<dim3(16, 16, 128), 256>>>(qkv, p, pos_bias_u, pos_bias_v, scores);
    softmax_kernel<<<128 * TT, 128>>>(scores);
    attnv_kernel<<<dim3(TT / 64, 128), 256>>>(scores, qkv, buf1);
    sgemm_kernel<<<dim3(DM / 128, NROW / 128), 256>>>(buf1, out_proj_w, out_proj_b, x, x, NROW, DM, DM, 0);

    // 4. conv module
    sgemm_kernel<<<dim3(1024 / 128, NROW / 128), 256>>>(x, conv_pw1_w, conv_pw1_b, nullptr, hid, NROW, DM, 1024, 0);
    glu_kernel<<<(NROW * DM) / 256, 256>>>(hid, buf1);
    dwconv_kernel<<<(NROW * DM) / 256, 256>>>(buf1, conv_dw_w, conv_dw_b, buf2);
    sgemm_kernel<<<dim3(DM / 128, NROW / 128), 256>>>(buf2, conv_pw2_w, conv_pw2_b, x, x, NROW, DM, DM, 0);

    // 5. second FFW
    sgemm_kernel<<<dim3(DFF / 128, NROW / 128), 256>>>(x, ff_w1, ff_b1, nullptr, hid, NROW, DM, DFF, 1);
    sgemm_kernel<<<dim3(DM / 128, NROW / 128), 256>>>(hid, ff_w2, ff_b2, x, x, NROW, DFF, DM, 0);

    // 6. BasicNorm -> output
    norm_kernel<<<NROW, 128>>>(x, (float*)d_out);
}

// round 4
// speedup vs baseline: 1.6971x; 1.6971x over previous
#include <cuda_runtime.h>
#include <cuda_bf16.h>
#include <cstdint>

// Shapes
#define TT 512
#define BB 16
#define DM 512
#define NH 8
#define HD 64
#define DFF 2048
#define NROW (TT*BB)          // 8192
#define EPS_BN 1.28402541668774148407f  // exp(0.25)

// ---------------- scratch (device globals; no allocation allowed) ----------------
__device__ float g_x[NROW*DM];
__device__ float g_hid[NROW*DFF];
__device__ float g_qkv[NROW*3*DM];
__device__ float g_pospad[1024*DM];
__device__ float g_p[1024*DM];
__device__ float g_scores[128*512*512];   // (B*H, T, T) fp32
__device__ float g_buf1[NROW*DM];
__device__ float g_buf2[NROW*DM];

// ================= helpers =================
__device__ __forceinline__ uint32_t smem_to_u32(const void* smem_ptr) {
    uint32_t addr;
    asm("{ .reg .u64 tmp; cvta.to.shared.u64 tmp, %1; cvt.u32.u64 %0, tmp; }"
        : "=r"(addr) : "l"(smem_ptr));
    return addr;
}

__device__ __forceinline__ void mma16816(float* c, const uint32_t* a, const uint32_t* b) {
    asm volatile("mma.sync.aligned.m16n8k16.row.col.f32.bf16.bf16.f32 "
        "{%0,%1,%2,%3},{%4,%5,%6,%7},{%8,%9},{%0,%1,%2,%3};"
        : "+f"(c[0]), "+f"(c[1]), "+f"(c[2]), "+f"(c[3])
        : "r"(a[0]), "r"(a[1]), "r"(a[2]), "r"(a[3]), "r"(b[0]), "r"(b[1]));
}

__device__ __forceinline__ void ldmx4(uint32_t* r, uint32_t addr) {
    asm volatile("ldmatrix.sync.aligned.m8n8.x4.shared.b16 {%0,%1,%2,%3}, [%4];"
        : "=r"(r[0]), "=r"(r[1]), "=r"(r[2]), "=r"(r[3]) : "r"(addr));
}

// split fp32x4 -> bf16 hi/lo (4 bf16 = 8B each) into smem
__device__ __forceinline__ void split_store(char* hi, char* lo, float4 v) {
    __nv_bfloat16 h0 = __float2bfloat16_rn(v.x), h1 = __float2bfloat16_rn(v.y);
    __nv_bfloat16 h2 = __float2bfloat16_rn(v.z), h3 = __float2bfloat16_rn(v.w);
    __nv_bfloat16 l0 = __float2bfloat16_rn(v.x - __bfloat162float(h0));
    __nv_bfloat16 l1 = __float2bfloat16_rn(v.y - __bfloat162float(h1));
    __nv_bfloat16 l2 = __float2bfloat16_rn(v.z - __bfloat162float(h2));
    __nv_bfloat16 l3 = __float2bfloat16_rn(v.w - __bfloat162float(h3));
    __nv_bfloat162 H0 = __halves2bfloat162(h0, h1), H1 = __halves2bfloat162(h2, h3);
    __nv_bfloat162 L0 = __halves2bfloat162(l0, l1), L1 = __halves2bfloat162(l2, l3);
    *(uint2*)hi = make_uint2(*(uint32_t*)&H0, *(uint32_t*)&H1);
    *(uint2*)lo = make_uint2(*(uint32_t*)&L0, *(uint32_t*)&L1);
}

// ---------------- tensor-core GEMM: C[.,M] = act(A[.,K] @ W[M,K]^T + bias) (+res) ----------------
// 3-term bf16 split via mma.sync (HMMA). grid=(M/128, rows/128), block=256.
// SMEM tiles padded to 80B row stride (conflict-free ldmatrix).
#define TILE_B   10240          // 128 rows * 80 bytes
#define GSM_BYTES (4*TILE_B)    // Ah, Al, Wh, Wl
__global__ __launch_bounds__(256, 1) void mma_gemm(
    const float* __restrict__ A, const float* __restrict__ W,
    const float* __restrict__ bias, const float* __restrict__ res,
    float* __restrict__ C, int K, int M, int act)
{
    extern __shared__ char smem[];
    const int tid = threadIdx.x;
    const int lane = tid & 31, warp = tid >> 5;
    const int wm = warp >> 2, wn = warp & 3;      // 2 x 4 warp grid
    const long n0 = (long)blockIdx.y * 128;       // output row block
    const long m0 = (long)blockIdx.x * 128;       // output col block
    const uint32_t smem_u = smem_to_u32(smem);

    float acc[4][4][4];
#pragma unroll
    for (int i = 0; i < 4; i++)
#pragma unroll
        for (int j = 0; j < 4; j++)
#pragma unroll
            for (int q = 0; q < 4; q++) acc[i][j][q] = 0.f;

    // per-thread load mapping: 4 float4 per tile (128 rows x 8 float4)
    int lrow[4], lf4[4];
#pragma unroll
    for (int i = 0; i < 4; i++) {
        int idx = tid + i * 256;
        lrow[i] = idx >> 3; lf4[i] = idx & 7;
    }

    float4 pa[4], pw[4];
#pragma unroll
    for (int i = 0; i < 4; i++) {
        pa[i] = *(const float4*)(A + (n0 + lrow[i]) * K + lf4[i] * 4);
        pw[i] = *(const float4*)(W + (m0 + lrow[i]) * K + lf4[i] * 4);
    }

    const int ns = K >> 5;   // 32 fp32 per stage
    for (int s = 0; s < ns; s++) {
        // store split tiles
#pragma unroll
        for (int i = 0; i < 4; i++) {
            int boff = lrow[i] * 80 + lf4[i] * 8;
            split_store(smem + boff,              smem + TILE_B + boff,   pa[i]);
            split_store(smem + 2 * TILE_B + boff, smem + 3 * TILE_B + boff, pw[i]);
        }
        __syncthreads();
        // prefetch next stage
        if (s + 1 < ns) {
            int col = (s + 1) * 32;
#pragma unroll
            for (int i = 0; i < 4; i++) {
                pa[i] = *(const float4*)(A + (n0 + lrow[i]) * K + col + lf4[i] * 4);
                pw[i] = *(const float4*)(W + (m0 + lrow[i]) * K + col + lf4[i] * 4);
            }
        }
        // MMAs over two k16 blocks
        const int q = lane >> 3, r = lane & 7;
#pragma unroll
        for (int kb = 0; kb < 2; kb++) {
            uint32_t ah[4][4], al[4][4], bh[4][2], bl[4][2];
#pragma unroll
            for (int mt = 0; mt < 4; mt++) {
                uint32_t rowA = wm * 64 + mt * 16 + (q & 1) * 8 + r;
                uint32_t colk = kb * 16 + (q >> 1) * 8;
                uint32_t ad = smem_u + rowA * 80 + colk * 2;
                ldmx4(ah[mt], ad);
                ldmx4(al[mt], ad + TILE_B);
            }
#pragma unroll
            for (int p = 0; p < 2; p++) {
                uint32_t rowB = wn * 32 + p * 16 + (q >> 1) * 8 + r;
                uint32_t colk = kb * 16 + (q & 1) * 8;
                uint32_t bd = smem_u + 2 * TILE_B + rowB * 80 + colk * 2;
                uint32_t t0[4], t1[4];
                ldmx4(t0, bd);
                ldmx4(t1, bd + TILE_B);
                bh[2 * p][0] = t0[0]; bh[2 * p][1] = t0[1];
                bh[2 * p + 1][0] = t0[2]; bh[2 * p + 1][1] = t0[3];
                bl[2 * p][0] = t1[0]; bl[2 * p][1] = t1[1];
                bl[2 * p + 1][0] = t1[2]; bl[2 * p + 1][1] = t1[3];
            }
#pragma unroll
            for (int mt = 0; mt < 4; mt++)
#pragma unroll
                for (int nt = 0; nt < 4; nt++) {
                    mma16816(acc[mt][nt], ah[mt], bh[nt]);
                    mma16816(acc[mt][nt], ah[mt], bl[nt]);
                    mma16816(acc[mt][nt], al[mt], bh[nt]);
                }
        }
        __syncthreads();
    }

    // epilogue
    const int er = lane >> 2, ec = (lane & 3) * 2;
#pragma unroll
    for (int mt = 0; mt < 4; mt++) {
#pragma unroll
        for (int nt = 0; nt < 4; nt++) {
            long m = n0 + wm * 64 + mt * 16 + er;
            int n = (int)m0 + wn * 32 + nt * 8 + ec;
            float b0 = bias ? bias[n] : 0.f;
            float b1 = bias ? bias[n + 1] : 0.f;
#pragma unroll
            for (int half = 0; half < 2; half++) {
                long row = m + half * 8;
                float v0 = acc[mt][nt][half * 2 + 0] + b0;
                float v1 = acc[mt][nt][half * 2 + 1] + b1;
                if (act) {
                    v0 = v0 / (1.f + __expf(1.f - v0));
                    v1 = v1 / (1.f + __expf(1.f - v1));
                }
                if (res) {
                    v0 += res[row * M + n];
                    v1 += res[row * M + n + 1];
                }
                *(float2*)(C + row * M + n) = make_float2(v0, v1);
            }
        }
    }
}

// ---------------- pos_emb pad to 1024 rows ----------------
__global__ void pospad_kernel(const float* __restrict__ pe, float* __restrict__ out) {
    int idx = blockIdx.x * 256 + threadIdx.x;   // 1024*512
    out[idx] = (idx < 1023 * DM) ? pe[idx] : 0.f;
}

// ---------------- fused rel-pos attention scores: ac + rel_shift(bd) ----------------
__global__ __launch_bounds__(256) void scores_kernel(
    const float* __restrict__ qkv, const float* __restrict__ p,
    const float* __restrict__ ub, const float* __restrict__ vb,
    float* __restrict__ scores)
{
    __shared__ float squ[32][65], sqv[32][65], sk[32][65], sp[63][65];
    int bh = blockIdx.z; int b = bh >> 3; int h = bh & 7;
    int t0 = blockIdx.y * 32, s0 = blockIdx.x * 32;
    int tid = threadIdx.x;
#pragma unroll
    for (int i = 0; i < 8; i++) {
        int idx = tid + i * 256; int tl = idx >> 6; int d = idx & 63;
        float q = qkv[((t0 + tl) * BB + b) * (3 * DM) + h * HD + d] * 0.125f;
        squ[tl][d] = q + ub[h * HD + d];
        sqv[tl][d] = q + vb[h * HD + d];
        sk[tl][d]  = qkv[((s0 + tl) * BB + b) * (3 * DM) + DM + h * HD + d];
    }
    int base = (TT - 1) - (t0 + 31) + s0;
#pragma unroll
    for (int i = 0; i < 16; i++) {
        int idx = tid + i * 256;
        if (idx < 63 * 64) {
            int r = idx >> 6; int d = idx & 63;
            sp[r][d] = p[(base + r) * DM + h * HD + d];
        }
    }
    __syncthreads();
    int r = tid >> 4, c = tid & 15;
    float a00 = 0, a01 = 0, a10 = 0, a11 = 0;
#pragma unroll
    for (int d = 0; d < 64; d++) {
        float qu0 = squ[r][d],      qu1 = squ[r + 16][d];
        float qv0 = sqv[r][d],      qv1 = sqv[r + 16][d];
        float k0  = sk[c][d],       k1  = sk[c + 16][d];
        float p00 = sp[31 - r + c][d],      p01 = sp[31 - r + c + 16][d];
        float p10 = sp[15 - r + c][d],      p11 = sp[15 - r + c + 16][d];
        a00 += qu0 * k0 + qv0 * p00;
        a01 += qu0 * k1 + qv0 * p01;
        a10 += qu1 * k0 + qv1 * p10;
        a11 += qu1 * k1 + qv1 * p11;
    }
    float* out = scores + ((long)bh * TT) * TT;
    out[(t0 + r) * TT + s0 + c]            = a00;
    out[(t0 + r) * TT + s0 + c + 16]       = a01;
    out[(t0 + r + 16) * TT + s0 + c]       = a10;
    out[(t0 + r + 16) * TT + s0 + c + 16]  = a11;
}

// ---------------- softmax over last dim (512), in place ----------------
__global__ __launch_bounds__(128) void softmax_kernel(float* __restrict__ scores) {
    long row = blockIdx.x;
    float* x = scores + row * TT;
    int tid = threadIdx.x;
    __shared__ float red[128];
    float v[4];
    float m = -1e30f;
#pragma unroll
    for (int i = 0; i < 4; i++) { v[i] = x[tid + i * 128]; m = fmaxf(m, v[i]); }
    red[tid] = m; __syncthreads();
    for (int s = 64; s > 0; s >>= 1) { if (tid < s) red[tid] = fmaxf(red[tid], red[tid + s]); __syncthreads(); }
    m = red[0];
    float sum = 0.f;
#pragma unroll
    for (int i = 0; i < 4; i++) { v[i] = __expf(v[i] - m); sum += v[i]; }
    __syncthreads();
    red[tid] = sum; __syncthreads();
    for (int s = 64; s > 0; s >>= 1) { if (tid < s) red[tid] += red[tid + s]; __syncthreads(); }
    float inv = 1.f / red[0];
#pragma unroll
    for (int i = 0; i < 4; i++) x[tid + i * 128] = v[i] * inv;
}

// ---------------- attn @ V -> (T*B, DM) layout ----------------
__global__ __launch_bounds__(256) void attnv_kernel(
    const float* __restrict__ scores, const float* __restrict__ qkv, float* __restrict__ out)
{
    __shared__ float sa[64][33], sv[32][65];
    int bh = blockIdx.y; int b = bh >> 3, h = bh & 7;
    int t0 = blockIdx.x * 64;
    int tid = threadIdx.x;
    int tx = tid & 15, ty = tid >> 4;
    float acc[4][4];
#pragma unroll
    for (int i = 0; i < 4; i++)
#pragma unroll
        for (int j = 0; j < 4; j++) acc[i][j] = 0.f;
    const float* S = scores + ((long)bh * TT + t0) * TT;
    for (int sblk = 0; sblk < TT; sblk += 32) {
#pragma unroll
        for (int i = 0; i < 8; i++) {
            int idx = tid + i * 256; int rr = idx >> 5; int cc = idx & 31;
            sa[rr][cc] = S[rr * TT + sblk + cc];
        }
#pragma unroll
        for (int i = 0; i < 8; i++) {
            int idx = tid + i * 256; int rr = idx >> 6; int dd = idx & 63;
            sv[rr][dd] = qkv[((sblk + rr) * BB + b) * (3 * DM) + 2 * DM + h * HD + dd];
        }
        __syncthreads();
#pragma unroll
        for (int s = 0; s < 32; s++) {
            float a[4], vv[4];
#pragma unroll
            for (int i = 0; i < 4; i++) a[i] = sa[ty * 4 + i][s];
#pragma unroll
            for (int j = 0; j < 4; j++) vv[j] = sv[s][tx * 4 + j];
#pragma unroll
            for (int i = 0; i < 4; i++)
#pragma unroll
                for (int j = 0; j < 4; j++) acc[i][j] += a[i] * vv[j];
        }
        __syncthreads();
    }
#pragma unroll
    for (int i = 0; i < 4; i++) {
        int t = t0 + ty * 4 + i;
#pragma unroll
        for (int j = 0; j < 4; j++) {
            int d = tx * 4 + j;
            out[(t * BB + b) * DM + h * HD + d] = acc[i][j];
        }
    }
}

// ---------------- GLU over channel dim ----------------
__global__ void glu_kernel(const float* __restrict__ in, float* __restrict__ out) {
    int idx = blockIdx.x * 256 + threadIdx.x;      // NROW*512
    int row = idx >> 9, c = idx & 511;
    float a = in[row * 1024 + c], g = in[row * 1024 + 512 + c];
    out[idx] = a / (1.f + __expf(-g));
}

// ---------------- depthwise causal conv (K=31) + bias + double_swish ----------------
__global__ void dwconv_kernel(const float* __restrict__ x, const float* __restrict__ w,
                              const float* __restrict__ bias, float* __restrict__ out) {
    int idx = blockIdx.x * 256 + threadIdx.x;      // NROW*512
    int c = idx & 511;
    int tb = idx >> 9; int b = tb & 15; int t = tb >> 4;
    float acc = bias[c];
#pragma unroll
    for (int j = 0; j < 31; j++) {
        int tt = t - 30 + j;
        if (tt >= 0) acc += w[c * 31 + j] * x[(tt * BB + b) * DM + c];
    }
    out[idx] = acc / (1.f + __expf(1.f - acc));
}

// ---------------- BasicNorm ----------------
__global__ __launch_bounds__(128) void norm_kernel(const float* __restrict__ x, float* __restrict__ out) {
    int row = blockIdx.x; int tid = threadIdx.x;
    const float* xr = x + row * DM;
    __shared__ float red[128];
    float v[4]; float s = 0.f;
#pragma unroll
    for (int i = 0; i < 4; i++) { v[i] = xr[tid + i * 128]; s += v[i] * v[i]; }
    red[tid] = s; __syncthreads();
    for (int k = 64; k > 0; k >>= 1) { if (tid < k) red[tid] += red[tid + k]; __syncthreads(); }
    float scale = rsqrtf(red[0] * (1.f / DM) + EPS_BN);
#pragma unroll
    for (int i = 0; i < 4; i++) out[row * DM + tid + i * 128] = v[i] * scale;
}

// ---------------- launch ----------------
static void launch_gemm(const float* A, const float* W, const float* bias, const float* res,
                        float* C, int Nrows, int K, int M, int act) {
    static bool attr_set = false;
    if (!attr_set) {
        cudaFuncSetAttribute(mma_gemm, cudaFuncAttributeMaxDynamicSharedMemorySize, GSM_BYTES);
        attr_set = true;
    }
    mma_gemm<<<dim3(M / 128, Nrows / 128), 256, GSM_BYTES>>>(A, W, bias, res, C, K, M, act);
}

extern "C" void kernel_launch(void* const* d_in, const int* in_sizes, int n_in,
                              void* d_out, int out_size) {
    const float* src        = (const float*)d_in[0];
    const float* pos_emb    = (const float*)d_in[1];
    const float* ffm_w1     = (const float*)d_in[2];
    const float* ffm_b1     = (const float*)d_in[3];
    const float* ffm_w2     = (const float*)d_in[4];
    const float* ffm_b2     = (const float*)d_in[5];
    const float* ff_w1      = (const float*)d_in[6];
    const float* ff_b1      = (const float*)d_in[7];
    const float* ff_w2      = (const float*)d_in[8];
    const float* ff_b2      = (const float*)d_in[9];
    const float* in_proj_w  = (const float*)d_in[10];
    const float* in_proj_b  = (const float*)d_in[11];
    const float* out_proj_w = (const float*)d_in[12];
    const float* out_proj_b = (const float*)d_in[13];
    const float* linear_pos_w = (const float*)d_in[14];
    const float* pos_bias_u = (const float*)d_in[15];
    const float* pos_bias_v = (const float*)d_in[16];
    const float* conv_pw1_w = (const float*)d_in[17];
    const float* conv_pw1_b = (const float*)d_in[18];
    const float* conv_dw_w  = (const float*)d_in[19];
    const float* conv_dw_b  = (const float*)d_in[20];
    const float* conv_pw2_w = (const float*)d_in[21];
    const float* conv_pw2_b = (const float*)d_in[22];

    float *x, *hid, *qkv, *pospad, *p, *scores, *buf1, *buf2;
    cudaGetSymbolAddress((void**)&x, g_x);
    cudaGetSymbolAddress((void**)&hid, g_hid);
    cudaGetSymbolAddress((void**)&qkv, g_qkv);
    cudaGetSymbolAddress((void**)&pospad, g_pospad);
    cudaGetSymbolAddress((void**)&p, g_p);
    cudaGetSymbolAddress((void**)&scores, g_scores);
    cudaGetSymbolAddress((void**)&buf1, g_buf1);
    cudaGetSymbolAddress((void**)&buf2, g_buf2);

    // 1. macaron FFW
    launch_gemm(src, ffm_w1, ffm_b1, nullptr, hid, NROW, DM, DFF, 1);
    launch_gemm(hid, ffm_w2, ffm_b2, src, x, NROW, DFF, DM, 0);

    // 2. attention projections
    launch_gemm(x, in_proj_w, in_proj_b, nullptr, qkv, NROW, DM, 3 * DM, 0);
    pospad_kernel<<<(1024 * DM) / 256, 256>>>(pos_emb, pospad);
    launch_gemm(pospad, linear_pos_w, nullptr, nullptr, p, 1024, DM, DM, 0);

    // 3. scores + softmax + attn@V
    scores_kernel<<<dim3(16, 16, 128), 256>>>(qkv, p, pos_bias_u, pos_bias_v, scores);
    softmax_kernel<<<128 * TT, 128>>>(scores);
    attnv_kernel<<<dim3(TT / 64, 128), 256>>>(scores, qkv, buf1);
    launch_gemm(buf1, out_proj_w, out_proj_b, x, x, NROW, DM, DM, 0);

    // 4. conv module
    launch_gemm(x, conv_pw1_w, conv_pw1_b, nullptr, hid, NROW, DM, 1024, 0);
    glu_kernel<<<(NROW * DM) / 256, 256>>>(hid, buf1);
    dwconv_kernel<<<(NROW * DM) / 256, 256>>>(buf1, conv_dw_w, conv_dw_b, buf2);
    launch_gemm(buf2, conv_pw2_w, conv_pw2_b, x, x, NROW, DM, DM, 0);

    // 5. second FFW
    launch_gemm(x, ff_w1, ff_b1, nullptr, hid, NROW, DM, DFF, 1);
    launch_gemm(hid, ff_w2, ff_b2, x, x, NROW, DFF, DM, 0);

    // 6. BasicNorm -> output
    norm_kernel<<<NROW, 128>>>(x, (float*)d_out);
}

// round 5
// speedup vs baseline: 1.8961x; 1.1172x over previous
#include <cuda_runtime.h>
#include <cuda_bf16.h>
#include <cstdint>

// Shapes
#define TT 512
#define BB 16
#define DM 512
#define NH 8
#define HD 64
#define DFF 2048
#define NROW (TT*BB)          // 8192
#define EPS_BN 1.28402541668774148407f  // exp(0.25)

// ---------------- scratch (device globals; no allocation allowed) ----------------
__device__ float g_x[NROW*DM];
__device__ float g_hid[NROW*DFF];
__device__ float g_qkv[NROW*3*DM];
__device__ float g_pospad[1024*DM];
__device__ float g_p[1024*DM];
__device__ float g_scores[128*512*512];   // (B*H, T, T) fp32
__device__ float g_buf1[NROW*DM];
__device__ float g_buf2[NROW*DM];

// ================= helpers =================
__device__ __forceinline__ uint32_t f2tf32(float f) {
    uint32_t r;
    asm("cvt.rna.tf32.f32 %0, %1;" : "=r"(r) : "f"(f));
    return r;
}
__device__ __forceinline__ uint4 cvt4(float4 v) {
    return make_uint4(f2tf32(v.x), f2tf32(v.y), f2tf32(v.z), f2tf32(v.w));
}
__device__ __forceinline__ void mma_tf32(float* c, const uint32_t* a, const uint32_t* b) {
    asm volatile("mma.sync.aligned.m16n8k8.row.col.f32.tf32.tf32.f32 "
        "{%0,%1,%2,%3},{%4,%5,%6,%7},{%8,%9},{%0,%1,%2,%3};"
        : "+f"(c[0]), "+f"(c[1]), "+f"(c[2]), "+f"(c[3])
        : "r"(a[0]), "r"(a[1]), "r"(a[2]), "r"(a[3]), "r"(b[0]), "r"(b[1]));
}

// ---------------- TF32 tensor-core GEMM ----------------
// C[rows,M] = act(A[rows,K] @ W[M,K]^T + bias) (+res)
// CTA tile 128x256, 8 warps (2x4), warp tile 64x64, K staged 32.
// SMEM: stride-36-float rows (conflict-free frag LDS), double buffered.
#define SA 36
#define ASZ (128*SA)          // 4608 floats
#define WSZ (256*SA)          // 9216 floats
#define BUFF (ASZ+WSZ)        // 13824 floats
#define GSM_BYTES (2*BUFF*4)  // 110592 bytes
__global__ __launch_bounds__(256, 1) void tf32_gemm(
    const float* __restrict__ A, const float* __restrict__ W,
    const float* __restrict__ bias, const float* __restrict__ res,
    float* __restrict__ C, int K, int M, int act)
{
    extern __shared__ uint32_t sm[];
    const int tid = threadIdx.x;
    const int lane = tid & 31, warp = tid >> 5;
    const int wr = warp >> 2, wn = warp & 3;     // 2 x 4 warps, warp tile 64x64
    const int g = lane >> 2, t = lane & 3;
    const long n0 = (long)blockIdx.y * 128;
    const long m0 = (long)blockIdx.x * 256;

    float acc[4][8][4];
#pragma unroll
    for (int i = 0; i < 4; i++)
#pragma unroll
        for (int j = 0; j < 8; j++)
#pragma unroll
            for (int q = 0; q < 4; q++) acc[i][j][q] = 0.f;

    // fill mapping: A tile 128x32 (4 float4/thread), W tile 256x32 (8 float4/thread)
    int ar[4], ac[4], wrw[8], wc[8];
#pragma unroll
    for (int i = 0; i < 4; i++) { int idx = tid + i * 256; ar[i] = idx >> 3; ac[i] = (idx & 7) * 4; }
#pragma unroll
    for (int i = 0; i < 8; i++) { int idx = tid + i * 256; wrw[i] = idx >> 3; wc[i] = (idx & 7) * 4; }

    float4 pa[4], pw[8];
#pragma unroll
    for (int i = 0; i < 4; i++) pa[i] = *(const float4*)(A + (n0 + ar[i]) * K + ac[i]);
#pragma unroll
    for (int i = 0; i < 8; i++) pw[i] = *(const float4*)(W + (m0 + wrw[i]) * K + wc[i]);

    // store stage 0 into buffer 0
#pragma unroll
    for (int i = 0; i < 4; i++) *(uint4*)&sm[ar[i] * SA + ac[i]] = cvt4(pa[i]);
#pragma unroll
    for (int i = 0; i < 8; i++) *(uint4*)&sm[ASZ + wrw[i] * SA + wc[i]] = cvt4(pw[i]);
    __syncthreads();

    const int ns = K >> 5;
    for (int s = 0; s < ns; s++) {
        const uint32_t* buf = sm + (s & 1) * BUFF;
        // prefetch next stage
        if (s + 1 < ns) {
            int col = (s + 1) * 32;
#pragma unroll
            for (int i = 0; i < 4; i++) pa[i] = *(const float4*)(A + (n0 + ar[i]) * K + col + ac[i]);
#pragma unroll
            for (int i = 0; i < 8; i++) pw[i] = *(const float4*)(W + (m0 + wrw[i]) * K + col + wc[i]);
        }
        // compute: 4 k8 blocks
#pragma unroll
        for (int kb = 0; kb < 4; kb++) {
            const int ca = kb * 8 + t;
            uint32_t afr[4][4];
#pragma unroll
            for (int mt = 0; mt < 4; mt++) {
                int r0 = wr * 64 + mt * 16 + g;
                afr[mt][0] = buf[r0 * SA + ca];
                afr[mt][1] = buf[(r0 + 8) * SA + ca];
                afr[mt][2] = buf[r0 * SA + ca + 4];
                afr[mt][3] = buf[(r0 + 8) * SA + ca + 4];
            }
            uint32_t bfr[8][2];
#pragma unroll
            for (int nt = 0; nt < 8; nt++) {
                int n = wn * 64 + nt * 8 + g;
                bfr[nt][0] = buf[ASZ + n * SA + ca];
                bfr[nt][1] = buf[ASZ + n * SA + ca + 4];
            }
#pragma unroll
            for (int mt = 0; mt < 4; mt++)
#pragma unroll
                for (int nt = 0; nt < 8; nt++)
                    mma_tf32(acc[mt][nt], afr[mt], bfr[nt]);
        }
        // store next stage into the other buffer (safe: nobody reads it this stage)
        if (s + 1 < ns) {
            uint32_t* nb = sm + ((s + 1) & 1) * BUFF;
#pragma unroll
            for (int i = 0; i < 4; i++) *(uint4*)&nb[ar[i] * SA + ac[i]] = cvt4(pa[i]);
#pragma unroll
            for (int i = 0; i < 8; i++) *(uint4*)&nb[ASZ + wrw[i] * SA + wc[i]] = cvt4(pw[i]);
        }
        __syncthreads();
    }

    // epilogue
#pragma unroll
    for (int mt = 0; mt < 4; mt++) {
#pragma unroll
        for (int nt = 0; nt < 8; nt++) {
            long row0 = n0 + wr * 64 + mt * 16 + g;
            int col = (int)m0 + wn * 64 + nt * 8 + 2 * t;
            float b0 = bias ? bias[col] : 0.f;
            float b1 = bias ? bias[col + 1] : 0.f;
#pragma unroll
            for (int h = 0; h < 2; h++) {
                long row = row0 + h * 8;
                float v0 = acc[mt][nt][h * 2 + 0] + b0;
                float v1 = acc[mt][nt][h * 2 + 1] + b1;
                if (act) {
                    v0 = v0 / (1.f + __expf(1.f - v0));
                    v1 = v1 / (1.f + __expf(1.f - v1));
                }
                if (res) {
                    v0 += res[row * M + col];
                    v1 += res[row * M + col + 1];
                }
                *(float2*)(C + row * M + col) = make_float2(v0, v1);
            }
        }
    }
}

// ---------------- pos_emb pad to 1024 rows ----------------
__global__ void pospad_kernel(const float* __restrict__ pe, float* __restrict__ out) {
    int idx = blockIdx.x * 256 + threadIdx.x;   // 1024*512
    out[idx] = (idx < 1023 * DM) ? pe[idx] : 0.f;
}

// ---------------- fused rel-pos attention scores: ac + rel_shift(bd) ----------------
__global__ __launch_bounds__(256) void scores_kernel(
    const float* __restrict__ qkv, const float* __restrict__ p,
    const float* __restrict__ ub, const float* __restrict__ vb,
    float* __restrict__ scores)
{
    __shared__ float squ[32][65], sqv[32][65], sk[32][65], sp[63][65];
    int bh = blockIdx.z; int b = bh >> 3; int h = bh & 7;
    int t0 = blockIdx.y * 32, s0 = blockIdx.x * 32;
    int tid = threadIdx.x;
#pragma unroll
    for (int i = 0; i < 8; i++) {
        int idx = tid + i * 256; int tl = idx >> 6; int d = idx & 63;
        float q = qkv[((t0 + tl) * BB + b) * (3 * DM) + h * HD + d] * 0.125f;
        squ[tl][d] = q + ub[h * HD + d];
        sqv[tl][d] = q + vb[h * HD + d];
        sk[tl][d]  = qkv[((s0 + tl) * BB + b) * (3 * DM) + DM + h * HD + d];
    }
    int base = (TT - 1) - (t0 + 31) + s0;
#pragma unroll
    for (int i = 0; i < 16; i++) {
        int idx = tid + i * 256;
        if (idx < 63 * 64) {
            int r = idx >> 6; int d = idx & 63;
            sp[r][d] = p[(base + r) * DM + h * HD + d];
        }
    }
    __syncthreads();
    int r = tid >> 4, c = tid & 15;
    float a00 = 0, a01 = 0, a10 = 0, a11 = 0;
#pragma unroll
    for (int d = 0; d < 64; d++) {
        float qu0 = squ[r][d],      qu1 = squ[r + 16][d];
        float qv0 = sqv[r][d],      qv1 = sqv[r + 16][d];
        float k0  = sk[c][d],       k1  = sk[c + 16][d];
        float p00 = sp[31 - r + c][d],      p01 = sp[31 - r + c + 16][d];
        float p10 = sp[15 - r + c][d],      p11 = sp[15 - r + c + 16][d];
        a00 += qu0 * k0 + qv0 * p00;
        a01 += qu0 * k1 + qv0 * p01;
        a10 += qu1 * k0 + qv1 * p10;
        a11 += qu1 * k1 + qv1 * p11;
    }
    float* out = scores + ((long)bh * TT) * TT;
    out[(t0 + r) * TT + s0 + c]            = a00;
    out[(t0 + r) * TT + s0 + c + 16]       = a01;
    out[(t0 + r + 16) * TT + s0 + c]       = a10;
    out[(t0 + r + 16) * TT + s0 + c + 16]  = a11;
}

// ---------------- softmax over last dim (512), in place ----------------
__global__ __launch_bounds__(128) void softmax_kernel(float* __restrict__ scores) {
    long row = blockIdx.x;
    float* x = scores + row * TT;
    int tid = threadIdx.x;
    __shared__ float red[128];
    float v[4];
    float m = -1e30f;
#pragma unroll
    for (int i = 0; i < 4; i++) { v[i] = x[tid + i * 128]; m = fmaxf(m, v[i]); }
    red[tid] = m; __syncthreads();
    for (int s = 64; s > 0; s >>= 1) { if (tid < s) red[tid] = fmaxf(red[tid], red[tid + s]); __syncthreads(); }
    m = red[0];
    float sum = 0.f;
#pragma unroll
    for (int i = 0; i < 4; i++) { v[i] = __expf(v[i] - m); sum += v[i]; }
    __syncthreads();
    red[tid] = sum; __syncthreads();
    for (int s = 64; s > 0; s >>= 1) { if (tid < s) red[tid] += red[tid + s]; __syncthreads(); }
    float inv = 1.f / red[0];
#pragma unroll
    for (int i = 0; i < 4; i++) x[tid + i * 128] = v[i] * inv;
}

// ---------------- attn @ V -> (T*B, DM) layout ----------------
__global__ __launch_bounds__(256) void attnv_kernel(
    const float* __restrict__ scores, const float* __restrict__ qkv, float* __restrict__ out)
{
    __shared__ float sa[64][33], sv[32][65];
    int bh = blockIdx.y; int b = bh >> 3, h = bh & 7;
    int t0 = blockIdx.x * 64;
    int tid = threadIdx.x;
    int tx = tid & 15, ty = tid >> 4;
    float acc[4][4];
#pragma unroll
    for (int i = 0; i < 4; i++)
#pragma unroll
        for (int j = 0; j < 4; j++) acc[i][j] = 0.f;
    const float* S = scores + ((long)bh * TT + t0) * TT;
    for (int sblk = 0; sblk < TT; sblk += 32) {
#pragma unroll
        for (int i = 0; i < 8; i++) {
            int idx = tid + i * 256; int rr = idx >> 5; int cc = idx & 31;
            sa[rr][cc] = S[rr * TT + sblk + cc];
        }
#pragma unroll
        for (int i = 0; i < 8; i++) {
            int idx = tid + i * 256; int rr = idx >> 6; int dd = idx & 63;
            sv[rr][dd] = qkv[((sblk + rr) * BB + b) * (3 * DM) + 2 * DM + h * HD + dd];
        }
        __syncthreads();
#pragma unroll
        for (int s = 0; s < 32; s++) {
            float a[4], vv[4];
#pragma unroll
            for (int i = 0; i < 4; i++) a[i] = sa[ty * 4 + i][s];
#pragma unroll
            for (int j = 0; j < 4; j++) vv[j] = sv[s][tx * 4 + j];
#pragma unroll
            for (int i = 0; i < 4; i++)
#pragma unroll
                for (int j = 0; j < 4; j++) acc[i][j] += a[i] * vv[j];
        }
        __syncthreads();
    }
#pragma unroll
    for (int i = 0; i < 4; i++) {
        int t = t0 + ty * 4 + i;
#pragma unroll
        for (int j = 0; j < 4; j++) {
            int d = tx * 4 + j;
            out[(t * BB + b) * DM + h * HD + d] = acc[i][j];
        }
    }
}

// ---------------- GLU over channel dim ----------------
__global__ void glu_kernel(const float* __restrict__ in, float* __restrict__ out) {
    int idx = blockIdx.x * 256 + threadIdx.x;      // NROW*512
    int row = idx >> 9, c = idx & 511;
    float a = in[row * 1024 + c], g = in[row * 1024 + 512 + c];
    out[idx] = a / (1.f + __expf(-g));
}

// ---------------- depthwise causal conv (K=31) + bias + double_swish ----------------
__global__ void dwconv_kernel(const float* __restrict__ x, const float* __restrict__ w,
                              const float* __restrict__ bias, float* __restrict__ out) {
    int idx = blockIdx.x * 256 + threadIdx.x;      // NROW*512
    int c = idx & 511;
    int tb = idx >> 9; int b = tb & 15; int t = tb >> 4;
    float acc = bias[c];
#pragma unroll
    for (int j = 0; j < 31; j++) {
        int tt = t - 30 + j;
        if (tt >= 0) acc += w[c * 31 + j] * x[(tt * BB + b) * DM + c];
    }
    out[idx] = acc / (1.f + __expf(1.f - acc));
}

// ---------------- BasicNorm ----------------
__global__ __launch_bounds__(128) void norm_kernel(const float* __restrict__ x, float* __restrict__ out) {
    int row = blockIdx.x; int tid = threadIdx.x;
    const float* xr = x + row * DM;
    __shared__ float red[128];
    float v[4]; float s = 0.f;
#pragma unroll
    for (int i = 0; i < 4; i++) { v[i] = xr[tid + i * 128]; s += v[i] * v[i]; }
    red[tid] = s; __syncthreads();
    for (int k = 64; k > 0; k >>= 1) { if (tid < k) red[tid] += red[tid + k]; __syncthreads(); }
    float scale = rsqrtf(red[0] * (1.f / DM) + EPS_BN);
#pragma unroll
    for (int i = 0; i < 4; i++) out[row * DM + tid + i * 128] = v[i] * scale;
}

// ---------------- launch ----------------
static void launch_gemm(const float* A, const float* W, const float* bias, const float* res,
                        float* C, int Nrows, int K, int M, int act) {
    cudaFuncSetAttribute(tf32_gemm, cudaFuncAttributeMaxDynamicSharedMemorySize, GSM_BYTES);
    tf32_gemm<<<dim3(M / 256, Nrows / 128), 256, GSM_BYTES>>>(A, W, bias, res, C, K, M, act);
}

extern "C" void kernel_launch(void* const* d_in, const int* in_sizes, int n_in,
                              void* d_out, int out_size) {
    const float* src        = (const float*)d_in[0];
    const float* pos_emb    = (const float*)d_in[1];
    const float* ffm_w1     = (const float*)d_in[2];
    const float* ffm_b1     = (const float*)d_in[3];
    const float* ffm_w2     = (const float*)d_in[4];
    const float* ffm_b2     = (const float*)d_in[5];
    const float* ff_w1      = (const float*)d_in[6];
    const float* ff_b1      = (const float*)d_in[7];
    const float* ff_w2      = (const float*)d_in[8];
    const float* ff_b2      = (const float*)d_in[9];
    const float* in_proj_w  = (const float*)d_in[10];
    const float* in_proj_b  = (const float*)d_in[11];
    const float* out_proj_w = (const float*)d_in[12];
    const float* out_proj_b = (const float*)d_in[13];
    const float* linear_pos_w = (const float*)d_in[14];
    const float* pos_bias_u = (const float*)d_in[15];
    const float* pos_bias_v = (const float*)d_in[16];
    const float* conv_pw1_w = (const float*)d_in[17];
    const float* conv_pw1_b = (const float*)d_in[18];
    const float* conv_dw_w  = (const float*)d_in[19];
    const float* conv_dw_b  = (const float*)d_in[20];
    const float* conv_pw2_w = (const float*)d_in[21];
    const float* conv_pw2_b = (const float*)d_in[22];

    float *x, *hid, *qkv, *pospad, *p, *scores, *buf1, *buf2;
    cudaGetSymbolAddress((void**)&x, g_x);
    cudaGetSymbolAddress((void**)&hid, g_hid);
    cudaGetSymbolAddress((void**)&qkv, g_qkv);
    cudaGetSymbolAddress((void**)&pospad, g_pospad);
    cudaGetSymbolAddress((void**)&p, g_p);
    cudaGetSymbolAddress((void**)&scores, g_scores);
    cudaGetSymbolAddress((void**)&buf1, g_buf1);
    cudaGetSymbolAddress((void**)&buf2, g_buf2);

    // 1. macaron FFW
    launch_gemm(src, ffm_w1, ffm_b1, nullptr, hid, NROW, DM, DFF, 1);
    launch_gemm(hid, ffm_w2, ffm_b2, src, x, NROW, DFF, DM, 0);

    // 2. attention projections
    launch_gemm(x, in_proj_w, in_proj_b, nullptr, qkv, NROW, DM, 3 * DM, 0);
    pospad_kernel<<<(1024 * DM) / 256, 256>>>(pos_emb, pospad);
    launch_gemm(pospad, linear_pos_w, nullptr, nullptr, p, 1024, DM, DM, 0);

    // 3. scores + softmax + attn@V
    scores_kernel<<<dim3(16, 16, 128), 256>>>(qkv, p, pos_bias_u, pos_bias_v, scores);
    softmax_kernel<<<128 * TT, 128>>>(scores);
    attnv_kernel<<<dim3(TT / 64, 128), 256>>>(scores, qkv, buf1);
    launch_gemm(buf1, out_proj_w, out_proj_b, x, x, NROW, DM, DM, 0);

    // 4. conv module
    launch_gemm(x, conv_pw1_w, conv_pw1_b, nullptr, hid, NROW, DM, 1024, 0);
    glu_kernel<<<(NROW * DM) / 256, 256>>>(hid, buf1);
    dwconv_kernel<<<(NROW * DM) / 256, 256>>>(buf1, conv_dw_w, conv_dw_b, buf2);
    launch_gemm(buf2, conv_pw2_w, conv_pw2_b, x, x, NROW, DM, DM, 0);

    // 5. second FFW
    launch_gemm(x, ff_w1, ff_b1, nullptr, hid, NROW, DM, DFF, 1);
    launch_gemm(hid, ff_w2, ff_b2, x, x, NROW, DFF, DM, 0);

    // 6. BasicNorm -> output
    norm_kernel<<<NROW, 128>>>(x, (float*)d_out);
}